// round 8
// baseline (speedup 1.0000x reference)
#include <cuda_runtime.h>
#include <cuda_fp16.h>
#include <cstdint>

#define BB 4
#define NN 16384
#define KK 16
#define CC 64
#define ROWS (BB * NN)          // 65536
#define GROUPS8P (ROWS / 8)     // proj: groups of 8 rows = 8192
#define GROUPS8 (ROWS / 8)      // fused attn: groups of 8 points
#define TOTAL ((size_t)ROWS * CC)

// ---------------- scratch (static device globals) ---------------------------
__device__ __half2 g_kv[TOTAL];   // (ek, v) packed per (row, channel) — 16 MB
__device__ __half  g_h [TOTAL];   // pre-BN FFN output — 8 MB
__device__ float   g_sum [CC];    // BN stats accumulators
__device__ float   g_sum2[CC];

// ---------------- packed fp32x2 helpers (Blackwell FFMA2) --------------------
__device__ __forceinline__ unsigned long long pk2(float lo, float hi) {
    unsigned long long r;
    asm("mov.b64 %0, {%1, %2};" : "=l"(r) : "f"(lo), "f"(hi));
    return r;
}
__device__ __forceinline__ unsigned long long ffma2(
    unsigned long long a, unsigned long long b, unsigned long long c) {
    unsigned long long d;
    asm("fma.rn.f32x2 %0, %1, %2, %3;" : "=l"(d) : "l"(a), "l"(b), "l"(c));
    return d;
}
__device__ __forceinline__ unsigned long long add2(
    unsigned long long a, unsigned long long b) {
    unsigned long long d;
    asm("add.rn.f32x2 %0, %1, %2;" : "=l"(d) : "l"(a), "l"(b));
    return d;
}
__device__ __forceinline__ float hsum2(unsigned long long a) {
    float lo, hi;
    asm("mov.b64 {%0, %1}, %2;" : "=f"(lo), "=f"(hi) : "l"(a));
    return lo + hi;
}

// ============================================================================
// Kernel 1: fused k/v projection, v4 — shuffle reduction, no partial-sum smem.
// Thread = (kq = lane&3 : 16-K slice, c = tid>>2 : out channel). The 4
// K-slice partials for a channel live in adjacent lanes of ONE warp, so the
// reduction is 2 shfl_xor butterflies (no smem round trip, no reduce pass).
// feat staged ONCE per block (coalesced LDG -> LDS broadcast), 8 rows per
// group, ping-pong staging = 1 barrier/group, packed f32x2 FMAs in 4
// independent chains. After the butterfly, lane kq keeps rows 2kq,2kq+1 so
// exp/pack/store work is spread across all lanes. smem = 4 KB -> high occ.
// ============================================================================
__global__ void __launch_bounds__(256, 4) proj_kernel(
    const float* __restrict__ feat,
    const float* __restrict__ kw, const float* __restrict__ kb,
    const float* __restrict__ vw, const float* __restrict__ vb)
{
    __shared__ float xs[2][8 * 64];          // staged rows, ping-pong (4 KB)

    const int tid  = threadIdx.x;
    const int lane = tid & 31;
    const int kq   = lane & 3;               // K-slice
    const int c    = tid >> 2;               // output channel 0..63

    if (blockIdx.x == 0 && tid < CC) { g_sum[tid] = 0.f; g_sum2[tid] = 0.f; }

    // weights for K-slice [kq*16, kq*16+16), channel c, packed as f32x2 pairs
    unsigned long long wk2[8], wv2[8];
#pragma unroll
    for (int i = 0; i < 8; i++) {
        wk2[i] = pk2(kw[(kq * 16 + 2 * i) * CC + c], kw[(kq * 16 + 2 * i + 1) * CC + c]);
        wv2[i] = pk2(vw[(kq * 16 + 2 * i) * CC + c], vw[(kq * 16 + 2 * i + 1) * CC + c]);
    }
    const float kbias = kb[c];
    const float vbias = vb[c];

    // prologue: stage first group (8 rows = 256 float2, one per thread)
    int g = blockIdx.x;
    ((float2*)xs[0])[tid] = ((const float2*)feat)[(size_t)g * 256 + tid];
    __syncthreads();

    int buf = 0;
    for (; g < GROUPS8P; g += gridDim.x) {
        const int  gn  = g + gridDim.x;
        const bool has = (gn < GROUPS8P);
        float2 pre;
        if (has) pre = ((const float2*)feat)[(size_t)gn * 256 + tid];  // LDG early

        float sk0 = 0.f, sv0 = 0.f, sk1 = 0.f, sv1 = 0.f;  // rows 2kq, 2kq+1

#pragma unroll
        for (int r = 0; r < 8; r++) {
            const ulonglong2* x2 = (const ulonglong2*)(xs[buf] + r * 64 + kq * 16);
            ulonglong2 qa = x2[0];   // floats 0..3 of the slice
            ulonglong2 qb = x2[1];   // floats 4..7
            ulonglong2 qc = x2[2];   // floats 8..11
            ulonglong2 qd = x2[3];   // floats 12..15

            // 4 independent FMA chains (k0,k1,v0,v1)
            unsigned long long ak0 = ffma2(qa.x, wk2[0], 0ULL);
            unsigned long long av0 = ffma2(qa.x, wv2[0], 0ULL);
            unsigned long long ak1 = ffma2(qc.x, wk2[4], 0ULL);
            unsigned long long av1 = ffma2(qc.x, wv2[4], 0ULL);
            ak0 = ffma2(qa.y, wk2[1], ak0);  av0 = ffma2(qa.y, wv2[1], av0);
            ak1 = ffma2(qc.y, wk2[5], ak1);  av1 = ffma2(qc.y, wv2[5], av1);
            ak0 = ffma2(qb.x, wk2[2], ak0);  av0 = ffma2(qb.x, wv2[2], av0);
            ak1 = ffma2(qd.x, wk2[6], ak1);  av1 = ffma2(qd.x, wv2[6], av1);
            ak0 = ffma2(qb.y, wk2[3], ak0);  av0 = ffma2(qb.y, wv2[3], av0);
            ak1 = ffma2(qd.y, wk2[7], ak1);  av1 = ffma2(qd.y, wv2[7], av1);

            float sk = hsum2(add2(ak0, ak1));
            float sv = hsum2(add2(av0, av1));

            // butterfly over the 4 kq lanes sharing this channel
            sk += __shfl_xor_sync(0xffffffffu, sk, 1);
            sv += __shfl_xor_sync(0xffffffffu, sv, 1);
            sk += __shfl_xor_sync(0xffffffffu, sk, 2);
            sv += __shfl_xor_sync(0xffffffffu, sv, 2);

            // lane kq keeps rows 2kq and 2kq+1 for the epilogue
            if ((r >> 1) == kq) {
                if (r & 1) { sk1 = sk; sv1 = sv; }
                else       { sk0 = sk; sv0 = sv; }
            }
        }

        // epilogue: 2 outputs per thread (exp spread across all lanes)
        {
            const size_t obase = (size_t)g * 512 + (size_t)(2 * kq) * 64 + c;
            float ekA = __expf(-(sk0 + kbias) * 0.125f);   // exp(-k/8): q cancels
            float ekB = __expf(-(sk1 + kbias) * 0.125f);
            g_kv[obase]      = __floats2half2_rn(ekA, sv0 + vbias);
            g_kv[obase + 64] = __floats2half2_rn(ekB, sv1 + vbias);
        }

        if (has) ((float2*)xs[buf ^ 1])[tid] = pre;   // STS after compute
        __syncthreads();   // the ONLY barrier per group
        buf ^= 1;
    }
}

// ============================================================================
// Kernel 2: fused local attention + FFN GEMV + BN stat accumulation.
// (byte-identical to the 98.9us passing kernel)
// ============================================================================
__global__ void __launch_bounds__(256, 2) attn_ffn_kernel(
    const void* __restrict__ idx_raw,
    const float* __restrict__ fw, const float* __restrict__ fb)
{
    __shared__ float xs[8 * 64];     // ctx rows for 8 points
    __shared__ float ps[32 * 64];    // GEMV partials; reused for stat reduce

    const int tid  = threadIdx.x;
    const int lane = tid & 31;
    const int w    = tid >> 5;       // warp = which point in the group
    const int kq   = tid >> 6;       // GEMV: K-slice
    const int c    = tid & 63;       // GEMV: out channel

    const unsigned* pw = (const unsigned*)idx_raw;
    const bool is64 = ((pw[1] | pw[3] | pw[5] | pw[7]) == 0u);

    float fwreg[16];
#pragma unroll
    for (int i = 0; i < 16; i++) fwreg[i] = fw[(kq * 16 + i) * CC + c];
    const float fbias = fb[c];

    float acc_s = 0.f, acc_s2 = 0.f;

    for (int g = blockIdx.x; g < GROUPS8; g += gridDim.x) {
        // ---- attention: one warp per point, lane owns channels 2l, 2l+1 ----
        const int p = g * 8 + w;
        const int b = p >> 14;                 // N = 16384
        int nb = 0;
        if (lane < KK) {
            long long iv = is64 ? ((const long long*)idx_raw)[(size_t)p * KK + lane]
                                : (long long)((const int*)idx_raw)[(size_t)p * KK + lane];
            nb = b * NN + (int)iv;
        }

        float ex[KK], ey[KK], vx[KK], vy[KK];
        float sx = 0.f, sy = 0.f;
#pragma unroll
        for (int j = 0; j < KK; j++) {
            int off = __shfl_sync(0xffffffffu, nb, j);
            uint2 r = ((const uint2*)(g_kv + (size_t)off * CC))[lane];
            float2 f0 = __half22float2(*(__half2*)&r.x);
            float2 f1 = __half22float2(*(__half2*)&r.y);
            ex[j] = f0.x; vx[j] = f0.y;
            ey[j] = f1.x; vy[j] = f1.y;
            sx += f0.x;   sy += f1.x;
        }
        const float ix = __fdividef(1.f, sx);
        const float iy = __fdividef(1.f, sy);

        float mx = -3.402823466e38f, my = -3.402823466e38f;
#pragma unroll
        for (int j = 0; j < KK; j++) {
            mx = fmaxf(mx, fmaf(ex[j], ix, -1.f) * vx[j]);   // (softmax-1) * v
            my = fmaxf(my, fmaf(ey[j], iy, -1.f) * vy[j]);
        }
        ((float2*)(xs + w * 64))[lane] = make_float2(mx, my);
        __syncthreads();

        // ---- FFN GEMV on the 8 ctx rows (x broadcast from smem) ------------
#pragma unroll
        for (int row = 0; row < 8; row++) {
            float pacc = 0.f;
            const float4* x4 = (const float4*)(xs + row * 64 + kq * 16);
#pragma unroll
            for (int i4 = 0; i4 < 4; i4++) {
                float4 xv = x4[i4];
                pacc = fmaf(xv.x, fwreg[i4 * 4 + 0], pacc);
                pacc = fmaf(xv.y, fwreg[i4 * 4 + 1], pacc);
                pacc = fmaf(xv.z, fwreg[i4 * 4 + 2], pacc);
                pacc = fmaf(xv.w, fwreg[i4 * 4 + 3], pacc);
            }
            ps[(row * 4 + kq) * 64 + c] = pacc;
        }
        __syncthreads();

        // ---- reduce partials, store h (fp16), accumulate stats -------------
#pragma unroll
        for (int rpass = 0; rpass < 2; rpass++) {
            const int row = (tid >> 6) + rpass * 4;
            float h = ps[(row * 4 + 0) * 64 + c] + ps[(row * 4 + 1) * 64 + c]
                    + ps[(row * 4 + 2) * 64 + c] + ps[(row * 4 + 3) * 64 + c] + fbias;
            g_h[(size_t)(g * 8 + row) * CC + c] = __float2half_rn(h);
            acc_s  += h;
            acc_s2 += h * h;
        }
        __syncthreads();
    }

    // ---- block-level stat reduction -> global atomics ----------------------
    ps[tid] = acc_s;  __syncthreads();
    if (tid < CC)
        atomicAdd(&g_sum[tid],  ps[tid] + ps[tid + 64] + ps[tid + 128] + ps[tid + 192]);
    __syncthreads();
    ps[tid] = acc_s2; __syncthreads();
    if (tid < CC)
        atomicAdd(&g_sum2[tid], ps[tid] + ps[tid + 64] + ps[tid + 128] + ps[tid + 192]);
}

// ============================================================================
// Kernel 3: finalize. BN scale/shift from stats, then BN + LeakyReLU +
// residual. (byte-identical to the passing kernel)
// ============================================================================
__global__ void __launch_bounds__(256) final_kernel(
    const float* __restrict__ feat,
    const float* __restrict__ gamma, const float* __restrict__ beta,
    float* __restrict__ out)
{
    __shared__ float s_scale[CC], s_shift[CC];
    if (threadIdx.x < CC) {
        const int  cc   = threadIdx.x;
        const float inv = 1.f / (float)ROWS;
        float m    = g_sum[cc] * inv;
        float var  = g_sum2[cc] * inv - m * m;
        float rstd = rsqrtf(var + 1e-5f);
        float sc   = rstd * gamma[cc];
        s_scale[cc] = sc;
        s_shift[cc] = beta[cc] - m * sc;
    }
    __syncthreads();

    const size_t total4 = TOTAL / 4;                 // groups of 4 channels
    const uint2*  h2 = (const uint2*)g_h;            // 4 halves per uint2
    const float4* f4 = (const float4*)feat;
    float4*       o4 = (float4*)out;
    const size_t stride = (size_t)gridDim.x * blockDim.x * 2;

    for (size_t i = ((size_t)blockIdx.x * blockDim.x + threadIdx.x) * 2;
         i + 1 < total4; i += stride) {
#pragma unroll
        for (int u = 0; u < 2; u++) {
            const size_t ii = i + u;
            const int c0 = (int)(ii & 15) * 4;
            uint2 hr = h2[ii];
            float4 f = f4[ii];
            float2 ha = __half22float2(*(__half2*)&hr.x);
            float2 hb = __half22float2(*(__half2*)&hr.y);
            float r0 = ha.x * s_scale[c0 + 0] + s_shift[c0 + 0];
            float r1 = ha.y * s_scale[c0 + 1] + s_shift[c0 + 1];
            float r2 = hb.x * s_scale[c0 + 2] + s_shift[c0 + 2];
            float r3 = hb.y * s_scale[c0 + 3] + s_shift[c0 + 3];
            r0 = (r0 >= 0.f) ? r0 : 0.2f * r0;
            r1 = (r1 >= 0.f) ? r1 : 0.2f * r1;
            r2 = (r2 >= 0.f) ? r2 : 0.2f * r2;
            r3 = (r3 >= 0.f) ? r3 : 0.2f * r3;
            o4[ii] = make_float4(f.x + r0, f.y + r1, f.z + r2, f.w + r3);
        }
    }
}

// ============================================================================
// launch: features(0) pos(1) qw(2) qb(3) kw(4) kb(5) vw(6) vb(7)
//         fw(8) fb(9) gamma(10) beta(11) idx(12)
// pos / qw / qb are mathematically unused (q cancels inside softmax).
// ============================================================================
extern "C" void kernel_launch(void* const* d_in, const int* in_sizes, int n_in,
                              void* d_out, int out_size)
{
    const float* feat  = (const float*)d_in[0];
    const float* kw    = (const float*)d_in[4];
    const float* kb    = (const float*)d_in[5];
    const float* vw    = (const float*)d_in[6];
    const float* vb    = (const float*)d_in[7];
    const float* fw    = (const float*)d_in[8];
    const float* fb    = (const float*)d_in[9];
    const float* gamma = (const float*)d_in[10];
    const float* beta  = (const float*)d_in[11];
    const void*  idx   = (const void*)d_in[12];
    float* out = (float*)d_out;

    proj_kernel     <<<592, 256>>>(feat, kw, kb, vw, vb);   // 4 CTAs x 148 SMs
    attn_ffn_kernel <<<1184, 256>>>(idx, fw, fb);
    final_kernel    <<<1024, 256>>>(feat, gamma, beta, out);
}

// round 10
// speedup vs baseline: 1.4457x; 1.4457x over previous
#include <cuda_runtime.h>
#include <cuda_fp16.h>
#include <cstdint>

#define BB 4
#define NN 16384
#define KK 16
#define CC 64
#define ROWS (BB * NN)          // 65536
#define GROUPS32P (ROWS / 32)   // proj: rounds of 32 rows = 2048
#define GROUPS8 (ROWS / 8)      // fused attn: groups of 8 points
#define TOTAL ((size_t)ROWS * CC)

// ---------------- scratch (static device globals) ---------------------------
__device__ __half2 g_kv[TOTAL];   // (ek, v) packed per (row, channel) — 16 MB
__device__ __half  g_h [TOTAL];   // pre-BN FFN output — 8 MB
__device__ float   g_sum [CC];    // BN stats accumulators
__device__ float   g_sum2[CC];

// ---------------- packed fp32x2 helpers (Blackwell FFMA2) --------------------
__device__ __forceinline__ unsigned long long pk2(float lo, float hi) {
    unsigned long long r;
    asm("mov.b64 %0, {%1, %2};" : "=l"(r) : "f"(lo), "f"(hi));
    return r;
}
__device__ __forceinline__ unsigned long long ffma2(
    unsigned long long a, unsigned long long b, unsigned long long c) {
    unsigned long long d;
    asm("fma.rn.f32x2 %0, %1, %2, %3;" : "=l"(d) : "l"(a), "l"(b), "l"(c));
    return d;
}
__device__ __forceinline__ float hsum2(unsigned long long a) {
    float lo, hi;
    asm("mov.b64 {%0, %1}, %2;" : "=f"(lo), "=f"(hi) : "l"(a));
    return lo + hi;
}

// ============================================================================
// Kernel 1: fused k/v projection, v5 — no reduction, wavefront-minimal.
// Thread owns ONE full output channel c = (warp>>2)*32 + lane; accumulates
// the whole K=64 in registers as f32x2 K-pairs. Warp (w&3) processes rows
// 8*(w&3)..+7 of a 32-row round; warps 0-3 do channels 0-31, 4-7 do 32-63.
//   x:   ulonglong2 LDS at warp-uniform address -> 1 wavefront, and the
//        (x_2k, x_2k+1) pair is FFMA2's multiplier format (no packing movs).
//   w:   pre-packed K-pair ull in smem; lanes contiguous -> LDS.64, 2 wf.
//   Per k4-step/warp: 16 wavefronts vs 32 FFMA2 -> LDS and FMA pipes balanced.
// 16 independent FFMA2 chains/thread-warp; 1 barrier/round; ping-pong staging
// with prefetch. Epilogue: hsum2 + exp(-k/8) (q cancels), pack half2.
// ============================================================================
__global__ void __launch_bounds__(256, 3) proj_kernel(
    const float* __restrict__ feat,
    const float* __restrict__ kw, const float* __restrict__ kb,
    const float* __restrict__ vw, const float* __restrict__ vb)
{
    __shared__ unsigned long long wsmK[32 * 64];  // [k2][c] K-pairs, 16 KB
    __shared__ unsigned long long wsmV[32 * 64];  // 16 KB
    __shared__ float xs[2][32 * 64];              // 32 staged rows, ping-pong, 16 KB

    const int tid  = threadIdx.x;
    const int lane = tid & 31;
    const int w    = tid >> 5;
    const int rw   = w & 3;                       // row subset 0..3
    const int c    = ((w >> 2) << 5) | lane;      // output channel 0..63

    if (blockIdx.x == 0 && tid < CC) { g_sum[tid] = 0.f; g_sum2[tid] = 0.f; }

    // one-time: pack weights into smem as (w_{2k2}[c], w_{2k2+1}[c]) pairs
    for (int i = tid; i < 32 * 64; i += 256) {
        const int k2 = i >> 6, ch = i & 63;
        wsmK[i] = pk2(kw[(2 * k2) * CC + ch], kw[(2 * k2 + 1) * CC + ch]);
        wsmV[i] = pk2(vw[(2 * k2) * CC + ch], vw[(2 * k2 + 1) * CC + ch]);
    }
    const float kbias = kb[c];
    const float vbias = vb[c];

    // prologue: stage first round (32 rows = 512 float4, 2 per thread)
    int g = blockIdx.x;
    {
        const float4* f4 = (const float4*)feat;
        ((float4*)xs[0])[tid]       = f4[(size_t)g * 512 + tid];
        ((float4*)xs[0])[tid + 256] = f4[(size_t)g * 512 + tid + 256];
    }
    __syncthreads();

    int buf = 0;
    for (; g < GROUPS32P; g += gridDim.x) {
        const int  gn  = g + gridDim.x;
        const bool has = (gn < GROUPS32P);
        float4 p0, p1;
        if (has) {
            const float4* f4 = (const float4*)feat;
            p0 = f4[(size_t)gn * 512 + tid];
            p1 = f4[(size_t)gn * 512 + tid + 256];
        }

        unsigned long long aK[8], aV[8];
#pragma unroll
        for (int r = 0; r < 8; r++) { aK[r] = 0ULL; aV[r] = 0ULL; }

        const float* xrow = xs[buf] + rw * (8 * 64);
#pragma unroll
        for (int k4 = 0; k4 < 16; k4++) {
            const unsigned long long wka = wsmK[(2 * k4) * 64 + c];
            const unsigned long long wkb = wsmK[(2 * k4 + 1) * 64 + c];
            const unsigned long long wva = wsmV[(2 * k4) * 64 + c];
            const unsigned long long wvb = wsmV[(2 * k4 + 1) * 64 + c];
#pragma unroll
            for (int r = 0; r < 8; r++) {
                ulonglong2 xq = *(const ulonglong2*)(xrow + r * 64 + k4 * 4);
                aK[r] = ffma2(xq.x, wka, aK[r]);
                aV[r] = ffma2(xq.x, wva, aV[r]);
                aK[r] = ffma2(xq.y, wkb, aK[r]);
                aV[r] = ffma2(xq.y, wvb, aV[r]);
            }
        }

        // epilogue: 8 outputs per thread
        const size_t obase = (size_t)g * (32 * 64) + (size_t)rw * (8 * 64) + c;
#pragma unroll
        for (int r = 0; r < 8; r++) {
            float sk = hsum2(aK[r]) + kbias;
            float sv = hsum2(aV[r]) + vbias;
            float ek = __expf(-sk * 0.125f);      // exp(-k/8): q cancels in softmax
            g_kv[obase + r * 64] = __floats2half2_rn(ek, sv);
        }

        if (has) {
            ((float4*)xs[buf ^ 1])[tid]       = p0;   // STS after compute
            ((float4*)xs[buf ^ 1])[tid + 256] = p1;
        }
        __syncthreads();   // the ONLY barrier per round
        buf ^= 1;
    }
}

// ============================================================================
// Kernel 2: fused local attention + FFN GEMV + BN stat accumulation.
// (byte-identical to the 98.9us passing kernel)
// ============================================================================
__global__ void __launch_bounds__(256, 2) attn_ffn_kernel(
    const void* __restrict__ idx_raw,
    const float* __restrict__ fw, const float* __restrict__ fb)
{
    __shared__ float xs[8 * 64];     // ctx rows for 8 points
    __shared__ float ps[32 * 64];    // GEMV partials; reused for stat reduce

    const int tid  = threadIdx.x;
    const int lane = tid & 31;
    const int w    = tid >> 5;       // warp = which point in the group
    const int kq   = tid >> 6;       // GEMV: K-slice
    const int c    = tid & 63;       // GEMV: out channel

    const unsigned* pw = (const unsigned*)idx_raw;
    const bool is64 = ((pw[1] | pw[3] | pw[5] | pw[7]) == 0u);

    float fwreg[16];
#pragma unroll
    for (int i = 0; i < 16; i++) fwreg[i] = fw[(kq * 16 + i) * CC + c];
    const float fbias = fb[c];

    float acc_s = 0.f, acc_s2 = 0.f;

    for (int g = blockIdx.x; g < GROUPS8; g += gridDim.x) {
        // ---- attention: one warp per point, lane owns channels 2l, 2l+1 ----
        const int p = g * 8 + w;
        const int b = p >> 14;                 // N = 16384
        int nb = 0;
        if (lane < KK) {
            long long iv = is64 ? ((const long long*)idx_raw)[(size_t)p * KK + lane]
                                : (long long)((const int*)idx_raw)[(size_t)p * KK + lane];
            nb = b * NN + (int)iv;
        }

        float ex[KK], ey[KK], vx[KK], vy[KK];
        float sx = 0.f, sy = 0.f;
#pragma unroll
        for (int j = 0; j < KK; j++) {
            int off = __shfl_sync(0xffffffffu, nb, j);
            uint2 r = ((const uint2*)(g_kv + (size_t)off * CC))[lane];
            float2 f0 = __half22float2(*(__half2*)&r.x);
            float2 f1 = __half22float2(*(__half2*)&r.y);
            ex[j] = f0.x; vx[j] = f0.y;
            ey[j] = f1.x; vy[j] = f1.y;
            sx += f0.x;   sy += f1.x;
        }
        const float ix = __fdividef(1.f, sx);
        const float iy = __fdividef(1.f, sy);

        float mx = -3.402823466e38f, my = -3.402823466e38f;
#pragma unroll
        for (int j = 0; j < KK; j++) {
            mx = fmaxf(mx, fmaf(ex[j], ix, -1.f) * vx[j]);   // (softmax-1) * v
            my = fmaxf(my, fmaf(ey[j], iy, -1.f) * vy[j]);
        }
        ((float2*)(xs + w * 64))[lane] = make_float2(mx, my);
        __syncthreads();

        // ---- FFN GEMV on the 8 ctx rows (x broadcast from smem) ------------
#pragma unroll
        for (int row = 0; row < 8; row++) {
            float pacc = 0.f;
            const float4* x4 = (const float4*)(xs + row * 64 + kq * 16);
#pragma unroll
            for (int i4 = 0; i4 < 4; i4++) {
                float4 xv = x4[i4];
                pacc = fmaf(xv.x, fwreg[i4 * 4 + 0], pacc);
                pacc = fmaf(xv.y, fwreg[i4 * 4 + 1], pacc);
                pacc = fmaf(xv.z, fwreg[i4 * 4 + 2], pacc);
                pacc = fmaf(xv.w, fwreg[i4 * 4 + 3], pacc);
            }
            ps[(row * 4 + kq) * 64 + c] = pacc;
        }
        __syncthreads();

        // ---- reduce partials, store h (fp16), accumulate stats -------------
#pragma unroll
        for (int rpass = 0; rpass < 2; rpass++) {
            const int row = (tid >> 6) + rpass * 4;
            float h = ps[(row * 4 + 0) * 64 + c] + ps[(row * 4 + 1) * 64 + c]
                    + ps[(row * 4 + 2) * 64 + c] + ps[(row * 4 + 3) * 64 + c] + fbias;
            g_h[(size_t)(g * 8 + row) * CC + c] = __float2half_rn(h);
            acc_s  += h;
            acc_s2 += h * h;
        }
        __syncthreads();
    }

    // ---- block-level stat reduction -> global atomics ----------------------
    ps[tid] = acc_s;  __syncthreads();
    if (tid < CC)
        atomicAdd(&g_sum[tid],  ps[tid] + ps[tid + 64] + ps[tid + 128] + ps[tid + 192]);
    __syncthreads();
    ps[tid] = acc_s2; __syncthreads();
    if (tid < CC)
        atomicAdd(&g_sum2[tid], ps[tid] + ps[tid + 64] + ps[tid + 128] + ps[tid + 192]);
}

// ============================================================================
// Kernel 3: finalize. BN scale/shift from stats, then BN + LeakyReLU +
// residual. (byte-identical to the passing kernel)
// ============================================================================
__global__ void __launch_bounds__(256) final_kernel(
    const float* __restrict__ feat,
    const float* __restrict__ gamma, const float* __restrict__ beta,
    float* __restrict__ out)
{
    __shared__ float s_scale[CC], s_shift[CC];
    if (threadIdx.x < CC) {
        const int  cc   = threadIdx.x;
        const float inv = 1.f / (float)ROWS;
        float m    = g_sum[cc] * inv;
        float var  = g_sum2[cc] * inv - m * m;
        float rstd = rsqrtf(var + 1e-5f);
        float sc   = rstd * gamma[cc];
        s_scale[cc] = sc;
        s_shift[cc] = beta[cc] - m * sc;
    }
    __syncthreads();

    const size_t total4 = TOTAL / 4;                 // groups of 4 channels
    const uint2*  h2 = (const uint2*)g_h;            // 4 halves per uint2
    const float4* f4 = (const float4*)feat;
    float4*       o4 = (float4*)out;
    const size_t stride = (size_t)gridDim.x * blockDim.x * 2;

    for (size_t i = ((size_t)blockIdx.x * blockDim.x + threadIdx.x) * 2;
         i + 1 < total4; i += stride) {
#pragma unroll
        for (int u = 0; u < 2; u++) {
            const size_t ii = i + u;
            const int c0 = (int)(ii & 15) * 4;
            uint2 hr = h2[ii];
            float4 f = f4[ii];
            float2 ha = __half22float2(*(__half2*)&hr.x);
            float2 hb = __half22float2(*(__half2*)&hr.y);
            float r0 = ha.x * s_scale[c0 + 0] + s_shift[c0 + 0];
            float r1 = ha.y * s_scale[c0 + 1] + s_shift[c0 + 1];
            float r2 = hb.x * s_scale[c0 + 2] + s_shift[c0 + 2];
            float r3 = hb.y * s_scale[c0 + 3] + s_shift[c0 + 3];
            r0 = (r0 >= 0.f) ? r0 : 0.2f * r0;
            r1 = (r1 >= 0.f) ? r1 : 0.2f * r1;
            r2 = (r2 >= 0.f) ? r2 : 0.2f * r2;
            r3 = (r3 >= 0.f) ? r3 : 0.2f * r3;
            o4[ii] = make_float4(f.x + r0, f.y + r1, f.z + r2, f.w + r3);
        }
    }
}

// ============================================================================
// launch: features(0) pos(1) qw(2) qb(3) kw(4) kb(5) vw(6) vb(7)
//         fw(8) fb(9) gamma(10) beta(11) idx(12)
// pos / qw / qb are mathematically unused (q cancels inside softmax).
// ============================================================================
extern "C" void kernel_launch(void* const* d_in, const int* in_sizes, int n_in,
                              void* d_out, int out_size)
{
    const float* feat  = (const float*)d_in[0];
    const float* kw    = (const float*)d_in[4];
    const float* kb    = (const float*)d_in[5];
    const float* vw    = (const float*)d_in[6];
    const float* vb    = (const float*)d_in[7];
    const float* fw    = (const float*)d_in[8];
    const float* fb    = (const float*)d_in[9];
    const float* gamma = (const float*)d_in[10];
    const float* beta  = (const float*)d_in[11];
    const void*  idx   = (const void*)d_in[12];
    float* out = (float*)d_out;

    proj_kernel     <<<444, 256>>>(feat, kw, kb, vw, vb);   // 3 CTAs x 148 SMs
    attn_ffn_kernel <<<1184, 256>>>(idx, fw, fb);
    final_kernel    <<<1024, 256>>>(feat, gamma, beta, out);
}